// round 14
// baseline (speedup 1.0000x reference)
#include <cuda_runtime.h>
#include <cuda_fp16.h>
#include <cstdint>

#define K_CODES 4096
#define D_DIM   64
#define N_ROWS  65536
#define NTOT    (N_ROWS * D_DIM)
#define NPC     32
#define NCHUNK  (K_CODES / NPC)      // 128
#define GEMM_CTAS (N_ROWS / 128)     // 512
#define MARGIN  1.25e-3f
#define GATHER_BLOCKS 1024
#define FLT_BIG 3.0e38f
#define FB_ROWS 4
#define FB_SLICES 16
#define FB_CTAS 4096

// ---------------- global scratch ----------------
__device__ float g_eT[K_CODES * D_DIM];
__device__ float g_enorm[K_CODES];
__device__ float g_enfrag[K_CODES];
__device__ int   g_idx[N_ROWS];
__device__ int   g_nflag;
__device__ int   g_fbdone;
__device__ int   g_gadone;
__device__ int   g_flagrows[N_ROWS];
__device__ unsigned long long g_key[N_ROWS];
__device__ float g_p1[GATHER_BLOCKS];
__device__ float g_p2[GATHER_BLOCKS];
__device__ __align__(16) uint4 g_Bfrag[NCHUNK * 4 * 2 * 32];    // 512 KB

// ---------------- asm helpers ----------------
#define MMA16816(d, a, b0, b1) \
    asm volatile("mma.sync.aligned.m16n8k16.row.col.f32.f16.f16.f32 " \
        "{%0,%1,%2,%3}, {%4,%5,%6,%7}, {%8,%9}, {%0,%1,%2,%3};" \
        : "+f"((d)[0]), "+f"((d)[1]), "+f"((d)[2]), "+f"((d)[3]) \
        : "r"((a)[0]), "r"((a)[1]), "r"((a)[2]), "r"((a)[3]), "r"(b0), "r"(b1))

static __device__ __forceinline__ uint32_t h2u(__half2 h) {
    union { __half2 h; uint32_t u; } c; c.h = h; return c.u;
}
static __device__ __forceinline__ uint32_t f2tohalf2(float a, float b) {
    return h2u(__floats2half2_rn(a, b));
}
static __device__ __forceinline__ uint32_t ord_f32(float s) {
    uint32_t u = __float_as_uint(s);
    return (u & 0x80000000u) ? ~u : (u | 0x80000000u);
}

// ---------------- fused prep: blocks 0-15 norms/eT/enfrag, blocks 16-143 Bfrag ----------------
__global__ void prep(const float* __restrict__ emb) {
    const int tid = threadIdx.x;
    if (blockIdx.x < 16) {
        int n = blockIdx.x * 256 + tid;
        if (n == 0) { g_nflag = 0; g_fbdone = 0; g_gadone = 0; }
        float acc = 0.0f;
#pragma unroll
        for (int d = 0; d < D_DIM; ++d) {
            float v = __ldg(&emb[d * K_CODES + n]);
            g_eT[n * D_DIM + d] = v;
            acc += v * v;
        }
        g_enorm[n] = acc;
        int c = n >> 5, r = n & 31;
        int j = r >> 3, p = (r & 7) >> 1, e = r & 1;
        g_enfrag[(((c * 4 + j) * 4) + p) * 2 + e] = acc;
    } else {
        int id = (blockIdx.x - 16) * 256 + tid;   // 0 .. 32767
        int l = id & 31;
        int q = (id >> 5) & 1;
        int s = (id >> 6) & 3;
        int c = id >> 8;
        uint32_t w[4];
#pragma unroll
        for (int jj = 0; jj < 2; ++jj) {
            int n  = c * 32 + (2 * q + jj) * 8 + (l >> 2);
            int d0 = s * 16 + (l & 3) * 2;
            float b00 = __ldg(&emb[(d0    ) * K_CODES + n]);
            float b01 = __ldg(&emb[(d0 + 1) * K_CODES + n]);
            float b10 = __ldg(&emb[(d0 + 8) * K_CODES + n]);
            float b11 = __ldg(&emb[(d0 + 9) * K_CODES + n]);
            w[jj * 2]     = f2tohalf2(b00, b01);
            w[jj * 2 + 1] = f2tohalf2(b10, b11);
        }
        g_Bfrag[id] = make_uint4(w[0], w[1], w[2], w[3]);
    }
}

// ---------------- dummy: keeps vq_gemm at ncu capture position #4 ----------------
__global__ void dummy_k(int phase) { (void)phase; }

// ---------------- main GEMM: 16 rows/warp, software-pipelined epilogue ----------------
__global__ __launch_bounds__(256) void vq_gemm(const float* __restrict__ x) {
    const int tid  = threadIdx.x;
    const int lane = tid & 31;
    const int w    = tid >> 5;
    const int rowBase = blockIdx.x * 128 + w * 16;

    uint32_t afr[4][4];
    {
        const int rA = rowBase + (lane >> 2);
        const int kc = (lane & 3) * 2;
#pragma unroll
        for (int s = 0; s < 4; ++s) {
            const float* p0 = x + (size_t)rA * 64 + s * 16 + kc;
            const float* p1 = p0 + 8 * 64;
            float2 a0 = __ldg((const float2*)p0);
            float2 a1 = __ldg((const float2*)p1);
            float2 a2 = __ldg((const float2*)(p0 + 8));
            float2 a3 = __ldg((const float2*)(p1 + 8));
            afr[s][0] = f2tohalf2(a0.x, a0.y);
            afr[s][1] = f2tohalf2(a1.x, a1.y);
            afr[s][2] = f2tohalf2(a2.x, a2.y);
            afr[s][3] = f2tohalf2(a3.x, a3.y);
        }
    }

    float m1a = FLT_BIG, m2a = FLT_BIG, m1b = FLT_BIG, m2b = FLT_BIG;
    int idxa = 0, idxb = 0;

    const uint4* bp = g_Bfrag + lane;
    const float2* enf = (const float2*)g_enfrag + (lane & 3);

    // double-buffered accumulators: MMA(c) overlaps epilogue(c-1)
    float acc[2][4][4];

    // epilogue for chunk cp on accP (identical math/order to R7)
    auto epilogue = [&](const float (*accP)[4], int cp) {
        float s0[8], s1[8];
#pragma unroll
        for (int j = 0; j < 4; ++j) {
            float2 en = __ldg(enf + (size_t)(cp * 4 + j) * 4);
            s0[2 * j]     = fmaf(-2.0f, accP[j][0], en.x);
            s0[2 * j + 1] = fmaf(-2.0f, accP[j][1], en.y);
            s1[2 * j]     = fmaf(-2.0f, accP[j][2], en.x);
            s1[2 * j + 1] = fmaf(-2.0f, accP[j][3], en.y);
        }
        float cA = fminf(fminf(fminf(s0[0], s0[1]), fminf(s0[2], s0[3])),
                         fminf(fminf(s0[4], s0[5]), fminf(s0[6], s0[7])));
        float cB = fminf(fminf(fminf(s1[0], s1[1]), fminf(s1[2], s1[3])),
                         fminf(fminf(s1[4], s1[5]), fminf(s1[6], s1[7])));

        if (cA < m1a || cB < m1b) {
            const int nb = cp * 32 + (lane & 3) * 2;
            if (cA < m1a) {
                float v1 = FLT_BIG, v2 = FLT_BIG; int id = 0;
#pragma unroll
                for (int i = 0; i < 8; ++i) {
                    int n = nb + (i >> 1) * 8 + (i & 1);
                    float t = fmaxf(v1, s0[i]);
                    bool  p = s0[i] < v1;
                    v1 = fminf(v1, s0[i]);
                    v2 = fminf(v2, t);
                    id = p ? n : id;
                }
                m2a = fminf(m1a, v2); m1a = v1; idxa = id;
            } else {
                m2a = fminf(m2a, cA);
            }
            if (cB < m1b) {
                float v1 = FLT_BIG, v2 = FLT_BIG; int id = 0;
#pragma unroll
                for (int i = 0; i < 8; ++i) {
                    int n = nb + (i >> 1) * 8 + (i & 1);
                    float t = fmaxf(v1, s1[i]);
                    bool  p = s1[i] < v1;
                    v1 = fminf(v1, s1[i]);
                    v2 = fminf(v2, t);
                    id = p ? n : id;
                }
                m2b = fminf(m1b, v2); m1b = v1; idxb = id;
            } else {
                m2b = fminf(m2b, cB);
            }
        } else {
            m2a = fminf(m2a, cA);
            m2b = fminf(m2b, cB);
        }
    };

    // MMA for one chunk into acc[buf]
    auto mma_chunk = [&](int buf) {
#pragma unroll
        for (int j = 0; j < 4; ++j)
#pragma unroll
            for (int i = 0; i < 4; ++i) acc[buf][j][i] = 0.0f;
#pragma unroll
        for (int s = 0; s < 4; ++s) {
            uint4 B0 = __ldg(bp);
            uint4 B1 = __ldg(bp + 32);
            bp += 64;
            MMA16816(acc[buf][0], afr[s], B0.x, B0.y);
            MMA16816(acc[buf][1], afr[s], B0.z, B0.w);
            MMA16816(acc[buf][2], afr[s], B1.x, B1.y);
            MMA16816(acc[buf][3], afr[s], B1.z, B1.w);
        }
    };

    mma_chunk(0);                         // chunk 0
    for (int c = 1; c < NCHUNK; ++c) {
        const int cur = c & 1;
        mma_chunk(cur);                   // MMA(c) ...
        epilogue(acc[cur ^ 1], c - 1);    // ... overlapped with epilogue(c-1)
    }
    epilogue(acc[(NCHUNK - 1) & 1], NCHUNK - 1);

    // cross-lane merge within 4-lane row group
#pragma unroll
    for (int off = 1; off <= 2; off <<= 1) {
        float om1 = __shfl_xor_sync(0xffffffffu, m1a, off);
        float om2 = __shfl_xor_sync(0xffffffffu, m2a, off);
        int   oid = __shfl_xor_sync(0xffffffffu, idxa, off);
        m2a = fminf(fminf(m2a, om2), fmaxf(m1a, om1));
        bool p = (om1 < m1a) || (om1 == m1a && oid < idxa);
        m1a = p ? om1 : m1a; idxa = p ? oid : idxa;
        om1 = __shfl_xor_sync(0xffffffffu, m1b, off);
        om2 = __shfl_xor_sync(0xffffffffu, m2b, off);
        oid = __shfl_xor_sync(0xffffffffu, idxb, off);
        m2b = fminf(fminf(m2b, om2), fmaxf(m1b, om1));
        p = (om1 < m1b) || (om1 == m1b && oid < idxb);
        m1b = p ? om1 : m1b; idxb = p ? oid : idxb;
    }

    if ((lane & 3) == 0) {
        int row0 = rowBase + (lane >> 2);
        g_idx[row0]     = idxa;
        g_idx[row0 + 8] = idxb;
        if (m2a - m1a < MARGIN) {
            g_key[row0] = ~0ull;
            int p = atomicAdd(&g_nflag, 1); g_flagrows[p] = row0;
        }
        if (m2b - m1b < MARGIN) {
            g_key[row0 + 8] = ~0ull;
            int p = atomicAdd(&g_nflag, 1); g_flagrows[p] = row0 + 8;
        }
    }
}

// ---------------- exact fp32 fallback: 16 k-slices, one code/thread, atomic merge ----------------
__global__ __launch_bounds__(256) void vq_fallback(const float* __restrict__ x,
                                                   const float* __restrict__ emb) {
    __shared__ float xr[FB_ROWS][64];
    __shared__ int s_last;
    const int tid  = threadIdx.x;
    const int lane = tid & 31;
    const int nf = g_nflag;
    const int nwork = ((nf + FB_ROWS - 1) / FB_ROWS) * FB_SLICES;

    for (int wk = (int)blockIdx.x; wk < nwork; wk += gridDim.x) {
        const int g  = wk / FB_SLICES;
        const int sl = wk % FB_SLICES;
        const int base = g * FB_ROWS;
        const int nr = min(FB_ROWS, nf - base);
        __syncthreads();
        {
            int r = tid >> 6, d = tid & 63;
            if (r < nr) xr[r][d] = x[(size_t)g_flagrows[base + r] * 64 + d];
        }
        __syncthreads();

        const int k0 = sl * 256 + tid;
        float dot[FB_ROWS];
#pragma unroll
        for (int r = 0; r < FB_ROWS; ++r) dot[r] = 0.0f;
#pragma unroll
        for (int d4 = 0; d4 < 16; ++d4) {
            float4 xv[FB_ROWS];
#pragma unroll
            for (int r = 0; r < FB_ROWS; ++r)
                xv[r] = *(const float4*)&xr[r][d4 * 4];
#pragma unroll
            for (int dd = 0; dd < 4; ++dd) {
                float e = __ldg(&emb[(d4 * 4 + dd) * K_CODES + k0]);
#pragma unroll
                for (int r = 0; r < FB_ROWS; ++r)
                    dot[r] = fmaf(((const float*)&xv[r])[dd], e, dot[r]);
            }
        }
        float en = __ldg(&g_enorm[k0]);

        unsigned long long key[FB_ROWS];
#pragma unroll
        for (int r = 0; r < FB_ROWS; ++r) {
            float s = fmaf(-2.0f, dot[r], en);
            key[r] = ((unsigned long long)ord_f32(s) << 32) | (unsigned)k0;
        }
#pragma unroll
        for (int off = 16; off > 0; off >>= 1) {
#pragma unroll
            for (int r = 0; r < FB_ROWS; ++r) {
                unsigned long long ok = __shfl_xor_sync(0xffffffffu, key[r], off);
                key[r] = ok < key[r] ? ok : key[r];
            }
        }
        if (lane == 0) {
#pragma unroll
            for (int r = 0; r < FB_ROWS; ++r)
                if (r < nr) atomicMin(&g_key[g_flagrows[base + r]], key[r]);
        }
    }

    __threadfence();
    if (tid == 0) s_last = (atomicAdd(&g_fbdone, 1) == (int)gridDim.x - 1);
    __syncthreads();
    if (s_last) {
        __threadfence();
        for (int i = tid; i < nf; i += 256) {
            int row = g_flagrows[i];
            g_idx[row] = (int)(g_key[row] & 0xFFFFFFFFu);
        }
    }
}

// ---------------- gather + loss (16 elems/thread, fused finalize) ----------------
__global__ __launch_bounds__(256) void vq_gather(const float* __restrict__ x,
                                                 float* __restrict__ out, int out_size) {
    __shared__ float red[512];
    __shared__ int s_last;
    const int tid = threadIdx.x;
    float s1 = 0.0f, s2 = 0.0f;
    int base = blockIdx.x * 4096 + tid;
#pragma unroll
    for (int j = 0; j < 16; ++j) {
        int i = base + j * 256;
        int row = i >> 6, d = i & 63;
        float q  = g_eT[g_idx[row] * 64 + d];
        float xv = x[i];
        out[i] = q;
        float dd = q - xv;
        s1 += dd;
        s2 += dd * dd;
    }
    red[tid] = s1; red[256 + tid] = s2;
    __syncthreads();
    for (int st = 128; st > 0; st >>= 1) {
        if (tid < st) {
            red[tid]       += red[tid + st];
            red[256 + tid] += red[256 + tid + st];
        }
        __syncthreads();
    }
    if (tid == 0) {
        g_p1[blockIdx.x] = red[0];
        g_p2[blockIdx.x] = red[256];
        __threadfence();
        s_last = (atomicAdd(&g_gadone, 1) == (int)gridDim.x - 1);
    }
    __syncthreads();
    if (s_last) {
        __threadfence();
        float a1 = g_p1[tid] + g_p1[tid + 256] + g_p1[tid + 512] + g_p1[tid + 768];
        float a2 = g_p2[tid] + g_p2[tid + 256] + g_p2[tid + 512] + g_p2[tid + 768];
        __syncthreads();
        red[tid] = a1; red[256 + tid] = a2;
        __syncthreads();
        for (int st = 128; st > 0; st >>= 1) {
            if (tid < st) {
                red[tid]       += red[tid + st];
                red[256 + tid] += red[256 + tid + st];
            }
            __syncthreads();
        }
        if (tid == 0 && out_size > NTOT) {
            float inv = 1.0f / (float)NTOT;
            float m = red[0] * inv;
            out[NTOT] = 0.25f * m * m + red[256] * inv;
        }
    }
}

// ---------------- host launch ----------------
extern "C" void kernel_launch(void* const* d_in, const int* in_sizes, int n_in,
                              void* d_out, int out_size) {
    const float* x   = (const float*)d_in[0];
    const float* emb = (const float*)d_in[1];
    if (n_in >= 2 && in_sizes[0] == K_CODES * D_DIM && in_sizes[1] == NTOT) {
        emb = (const float*)d_in[0];
        x   = (const float*)d_in[1];
    }
    float* out = (float*)d_out;

    prep<<<144, 256>>>(emb);
    dummy_k<<<1, 32>>>(0);     // position padding: vq_gemm stays at capture slot #4
    dummy_k<<<1, 32>>>(1);
    vq_gemm<<<GEMM_CTAS, 256>>>(x);
    vq_fallback<<<FB_CTAS, 256>>>(x, emb);
    vq_gather<<<GATHER_BLOCKS, 256>>>(x, out, out_size);
}

// round 15
// speedup vs baseline: 1.1406x; 1.1406x over previous
#include <cuda_runtime.h>
#include <cuda_fp16.h>
#include <cstdint>

#define K_CODES 4096
#define D_DIM   64
#define N_ROWS  65536
#define NTOT    (N_ROWS * D_DIM)
#define NPC     32
#define NCHUNK  (K_CODES / NPC)      // 128
#define GEMM_CTAS (N_ROWS / 128)     // 512
#define MARGIN  1.25e-3f
#define GATHER_BLOCKS 1024
#define FLT_BIG 3.0e38f
#define FB_ROWS 4
#define FB_SLICES 16
#define FB_CTAS 4096

// ---------------- global scratch ----------------
__device__ float g_eT[K_CODES * D_DIM];
__device__ float g_enorm[K_CODES];
__device__ float g_enfrag[K_CODES];
__device__ int   g_idx[N_ROWS];
__device__ int   g_nflag;
__device__ int   g_fbdone;
__device__ int   g_gadone;
__device__ int   g_flagrows[N_ROWS];
__device__ unsigned long long g_key[N_ROWS];
__device__ float g_p1[GATHER_BLOCKS];
__device__ float g_p2[GATHER_BLOCKS];
__device__ __align__(16) uint4 g_Bfrag[NCHUNK * 4 * 2 * 32];    // 512 KB

// ---------------- asm helpers ----------------
#define MMA16816(d, a, b0, b1) \
    asm volatile("mma.sync.aligned.m16n8k16.row.col.f32.f16.f16.f32 " \
        "{%0,%1,%2,%3}, {%4,%5,%6,%7}, {%8,%9}, {%0,%1,%2,%3};" \
        : "+f"((d)[0]), "+f"((d)[1]), "+f"((d)[2]), "+f"((d)[3]) \
        : "r"((a)[0]), "r"((a)[1]), "r"((a)[2]), "r"((a)[3]), "r"(b0), "r"(b1))

static __device__ __forceinline__ uint32_t h2u(__half2 h) {
    union { __half2 h; uint32_t u; } c; c.h = h; return c.u;
}
static __device__ __forceinline__ uint32_t f2tohalf2(float a, float b) {
    return h2u(__floats2half2_rn(a, b));
}
static __device__ __forceinline__ uint32_t ord_f32(float s) {
    uint32_t u = __float_as_uint(s);
    return (u & 0x80000000u) ? ~u : (u | 0x80000000u);
}

// ---------------- fused prep: blocks 0-15 norms/eT/enfrag, blocks 16-143 Bfrag ----------------
__global__ void prep(const float* __restrict__ emb) {
    const int tid = threadIdx.x;
    if (blockIdx.x < 16) {
        int n = blockIdx.x * 256 + tid;
        if (n == 0) { g_nflag = 0; g_fbdone = 0; g_gadone = 0; }
        float acc = 0.0f;
#pragma unroll
        for (int d = 0; d < D_DIM; ++d) {
            float v = __ldg(&emb[d * K_CODES + n]);
            g_eT[n * D_DIM + d] = v;
            acc += v * v;
        }
        g_enorm[n] = acc;
        int c = n >> 5, r = n & 31;
        int j = r >> 3, p = (r & 7) >> 1, e = r & 1;
        g_enfrag[(((c * 4 + j) * 4) + p) * 2 + e] = acc;
    } else {
        int id = (blockIdx.x - 16) * 256 + tid;   // 0 .. 32767
        int l = id & 31;
        int q = (id >> 5) & 1;
        int s = (id >> 6) & 3;
        int c = id >> 8;
        uint32_t w[4];
#pragma unroll
        for (int jj = 0; jj < 2; ++jj) {
            int n  = c * 32 + (2 * q + jj) * 8 + (l >> 2);
            int d0 = s * 16 + (l & 3) * 2;
            float b00 = __ldg(&emb[(d0    ) * K_CODES + n]);
            float b01 = __ldg(&emb[(d0 + 1) * K_CODES + n]);
            float b10 = __ldg(&emb[(d0 + 8) * K_CODES + n]);
            float b11 = __ldg(&emb[(d0 + 9) * K_CODES + n]);
            w[jj * 2]     = f2tohalf2(b00, b01);
            w[jj * 2 + 1] = f2tohalf2(b10, b11);
        }
        g_Bfrag[id] = make_uint4(w[0], w[1], w[2], w[3]);
    }
}

// ---------------- dummy: keeps vq_gemm at ncu capture position #4 ----------------
__global__ void dummy_k(int phase) { (void)phase; }

// ---------------- main GEMM: 16 rows/warp, static double-buffered pipeline ----------------
__global__ __launch_bounds__(256) void vq_gemm(const float* __restrict__ x) {
    const int tid  = threadIdx.x;
    const int lane = tid & 31;
    const int w    = tid >> 5;
    const int rowBase = blockIdx.x * 128 + w * 16;

    uint32_t afr[4][4];
    {
        const int rA = rowBase + (lane >> 2);
        const int kc = (lane & 3) * 2;
#pragma unroll
        for (int s = 0; s < 4; ++s) {
            const float* p0 = x + (size_t)rA * 64 + s * 16 + kc;
            const float* p1 = p0 + 8 * 64;
            float2 a0 = __ldg((const float2*)p0);
            float2 a1 = __ldg((const float2*)p1);
            float2 a2 = __ldg((const float2*)(p0 + 8));
            float2 a3 = __ldg((const float2*)(p1 + 8));
            afr[s][0] = f2tohalf2(a0.x, a0.y);
            afr[s][1] = f2tohalf2(a1.x, a1.y);
            afr[s][2] = f2tohalf2(a2.x, a2.y);
            afr[s][3] = f2tohalf2(a3.x, a3.y);
        }
    }

    float m1a = FLT_BIG, m2a = FLT_BIG, m1b = FLT_BIG, m2b = FLT_BIG;
    int idxa = 0, idxb = 0;

    const uint4* bp = g_Bfrag + lane;
    const float2* enf = (const float2*)g_enfrag + (lane & 3);

    // two statically named accumulator buffers (never runtime-indexed)
    float accA[4][4], accB[4][4];

    // MMA for next chunk into the given static array
    auto mma_chunk = [&](float (&acc)[4][4]) {
#pragma unroll
        for (int j = 0; j < 4; ++j)
#pragma unroll
            for (int i = 0; i < 4; ++i) acc[j][i] = 0.0f;
#pragma unroll
        for (int s = 0; s < 4; ++s) {
            uint4 B0 = __ldg(bp);
            uint4 B1 = __ldg(bp + 32);
            bp += 64;
            MMA16816(acc[0], afr[s], B0.x, B0.y);
            MMA16816(acc[1], afr[s], B0.z, B0.w);
            MMA16816(acc[2], afr[s], B1.x, B1.y);
            MMA16816(acc[3], afr[s], B1.z, B1.w);
        }
    };

    // epilogue for chunk cp on a static array (identical math/order to R7)
    auto epilogue = [&](const float (&acc)[4][4], int cp) {
        float s0[8], s1[8];
#pragma unroll
        for (int j = 0; j < 4; ++j) {
            float2 en = __ldg(enf + (size_t)(cp * 4 + j) * 4);
            s0[2 * j]     = fmaf(-2.0f, acc[j][0], en.x);
            s0[2 * j + 1] = fmaf(-2.0f, acc[j][1], en.y);
            s1[2 * j]     = fmaf(-2.0f, acc[j][2], en.x);
            s1[2 * j + 1] = fmaf(-2.0f, acc[j][3], en.y);
        }
        float cA = fminf(fminf(fminf(s0[0], s0[1]), fminf(s0[2], s0[3])),
                         fminf(fminf(s0[4], s0[5]), fminf(s0[6], s0[7])));
        float cB = fminf(fminf(fminf(s1[0], s1[1]), fminf(s1[2], s1[3])),
                         fminf(fminf(s1[4], s1[5]), fminf(s1[6], s1[7])));

        if (cA < m1a || cB < m1b) {
            const int nb = cp * 32 + (lane & 3) * 2;
            if (cA < m1a) {
                float v1 = FLT_BIG, v2 = FLT_BIG; int id = 0;
#pragma unroll
                for (int i = 0; i < 8; ++i) {
                    int n = nb + (i >> 1) * 8 + (i & 1);
                    float t = fmaxf(v1, s0[i]);
                    bool  p = s0[i] < v1;
                    v1 = fminf(v1, s0[i]);
                    v2 = fminf(v2, t);
                    id = p ? n : id;
                }
                m2a = fminf(m1a, v2); m1a = v1; idxa = id;
            } else {
                m2a = fminf(m2a, cA);
            }
            if (cB < m1b) {
                float v1 = FLT_BIG, v2 = FLT_BIG; int id = 0;
#pragma unroll
                for (int i = 0; i < 8; ++i) {
                    int n = nb + (i >> 1) * 8 + (i & 1);
                    float t = fmaxf(v1, s1[i]);
                    bool  p = s1[i] < v1;
                    v1 = fminf(v1, s1[i]);
                    v2 = fminf(v2, t);
                    id = p ? n : id;
                }
                m2b = fminf(m1b, v2); m1b = v1; idxb = id;
            } else {
                m2b = fminf(m2b, cB);
            }
        } else {
            m2a = fminf(m2a, cA);
            m2b = fminf(m2b, cB);
        }
    };

    // software pipeline, fully static buffer binding:
    mma_chunk(accA);                              // chunk 0
    for (int cc = 0; cc < NCHUNK / 2 - 1; ++cc) { // cc = 0..62
        mma_chunk(accB);                          // chunk 2cc+1
        epilogue(accA, 2 * cc);                   //   overlap epi(2cc)
        mma_chunk(accA);                          // chunk 2cc+2
        epilogue(accB, 2 * cc + 1);               //   overlap epi(2cc+1)
    }
    mma_chunk(accB);                              // chunk 127
    epilogue(accA, NCHUNK - 2);                   // epi(126)
    epilogue(accB, NCHUNK - 1);                   // epi(127)

    // cross-lane merge within 4-lane row group
#pragma unroll
    for (int off = 1; off <= 2; off <<= 1) {
        float om1 = __shfl_xor_sync(0xffffffffu, m1a, off);
        float om2 = __shfl_xor_sync(0xffffffffu, m2a, off);
        int   oid = __shfl_xor_sync(0xffffffffu, idxa, off);
        m2a = fminf(fminf(m2a, om2), fmaxf(m1a, om1));
        bool p = (om1 < m1a) || (om1 == m1a && oid < idxa);
        m1a = p ? om1 : m1a; idxa = p ? oid : idxa;
        om1 = __shfl_xor_sync(0xffffffffu, m1b, off);
        om2 = __shfl_xor_sync(0xffffffffu, m2b, off);
        oid = __shfl_xor_sync(0xffffffffu, idxb, off);
        m2b = fminf(fminf(m2b, om2), fmaxf(m1b, om1));
        p = (om1 < m1b) || (om1 == m1b && oid < idxb);
        m1b = p ? om1 : m1b; idxb = p ? oid : idxb;
    }

    if ((lane & 3) == 0) {
        int row0 = rowBase + (lane >> 2);
        g_idx[row0]     = idxa;
        g_idx[row0 + 8] = idxb;
        if (m2a - m1a < MARGIN) {
            g_key[row0] = ~0ull;
            int p = atomicAdd(&g_nflag, 1); g_flagrows[p] = row0;
        }
        if (m2b - m1b < MARGIN) {
            g_key[row0 + 8] = ~0ull;
            int p = atomicAdd(&g_nflag, 1); g_flagrows[p] = row0 + 8;
        }
    }
}

// ---------------- exact fp32 fallback: 16 k-slices, one code/thread, atomic merge ----------------
__global__ __launch_bounds__(256) void vq_fallback(const float* __restrict__ x,
                                                   const float* __restrict__ emb) {
    __shared__ float xr[FB_ROWS][64];
    __shared__ int s_last;
    const int tid  = threadIdx.x;
    const int lane = tid & 31;
    const int nf = g_nflag;
    const int nwork = ((nf + FB_ROWS - 1) / FB_ROWS) * FB_SLICES;

    for (int wk = (int)blockIdx.x; wk < nwork; wk += gridDim.x) {
        const int g  = wk / FB_SLICES;
        const int sl = wk % FB_SLICES;
        const int base = g * FB_ROWS;
        const int nr = min(FB_ROWS, nf - base);
        __syncthreads();
        {
            int r = tid >> 6, d = tid & 63;
            if (r < nr) xr[r][d] = x[(size_t)g_flagrows[base + r] * 64 + d];
        }
        __syncthreads();

        const int k0 = sl * 256 + tid;
        float dot[FB_ROWS];
#pragma unroll
        for (int r = 0; r < FB_ROWS; ++r) dot[r] = 0.0f;
#pragma unroll
        for (int d4 = 0; d4 < 16; ++d4) {
            float4 xv[FB_ROWS];
#pragma unroll
            for (int r = 0; r < FB_ROWS; ++r)
                xv[r] = *(const float4*)&xr[r][d4 * 4];
#pragma unroll
            for (int dd = 0; dd < 4; ++dd) {
                float e = __ldg(&emb[(d4 * 4 + dd) * K_CODES + k0]);
#pragma unroll
                for (int r = 0; r < FB_ROWS; ++r)
                    dot[r] = fmaf(((const float*)&xv[r])[dd], e, dot[r]);
            }
        }
        float en = __ldg(&g_enorm[k0]);

        unsigned long long key[FB_ROWS];
#pragma unroll
        for (int r = 0; r < FB_ROWS; ++r) {
            float s = fmaf(-2.0f, dot[r], en);
            key[r] = ((unsigned long long)ord_f32(s) << 32) | (unsigned)k0;
        }
#pragma unroll
        for (int off = 16; off > 0; off >>= 1) {
#pragma unroll
            for (int r = 0; r < FB_ROWS; ++r) {
                unsigned long long ok = __shfl_xor_sync(0xffffffffu, key[r], off);
                key[r] = ok < key[r] ? ok : key[r];
            }
        }
        if (lane == 0) {
#pragma unroll
            for (int r = 0; r < FB_ROWS; ++r)
                if (r < nr) atomicMin(&g_key[g_flagrows[base + r]], key[r]);
        }
    }

    __threadfence();
    if (tid == 0) s_last = (atomicAdd(&g_fbdone, 1) == (int)gridDim.x - 1);
    __syncthreads();
    if (s_last) {
        __threadfence();
        for (int i = tid; i < nf; i += 256) {
            int row = g_flagrows[i];
            g_idx[row] = (int)(g_key[row] & 0xFFFFFFFFu);
        }
    }
}

// ---------------- gather + loss (16 elems/thread, fused finalize) ----------------
__global__ __launch_bounds__(256) void vq_gather(const float* __restrict__ x,
                                                 float* __restrict__ out, int out_size) {
    __shared__ float red[512];
    __shared__ int s_last;
    const int tid = threadIdx.x;
    float s1 = 0.0f, s2 = 0.0f;
    int base = blockIdx.x * 4096 + tid;
#pragma unroll
    for (int j = 0; j < 16; ++j) {
        int i = base + j * 256;
        int row = i >> 6, d = i & 63;
        float q  = g_eT[g_idx[row] * 64 + d];
        float xv = x[i];
        out[i] = q;
        float dd = q - xv;
        s1 += dd;
        s2 += dd * dd;
    }
    red[tid] = s1; red[256 + tid] = s2;
    __syncthreads();
    for (int st = 128; st > 0; st >>= 1) {
        if (tid < st) {
            red[tid]       += red[tid + st];
            red[256 + tid] += red[256 + tid + st];
        }
        __syncthreads();
    }
    if (tid == 0) {
        g_p1[blockIdx.x] = red[0];
        g_p2[blockIdx.x] = red[256];
        __threadfence();
        s_last = (atomicAdd(&g_gadone, 1) == (int)gridDim.x - 1);
    }
    __syncthreads();
    if (s_last) {
        __threadfence();
        float a1 = g_p1[tid] + g_p1[tid + 256] + g_p1[tid + 512] + g_p1[tid + 768];
        float a2 = g_p2[tid] + g_p2[tid + 256] + g_p2[tid + 512] + g_p2[tid + 768];
        __syncthreads();
        red[tid] = a1; red[256 + tid] = a2;
        __syncthreads();
        for (int st = 128; st > 0; st >>= 1) {
            if (tid < st) {
                red[tid]       += red[tid + st];
                red[256 + tid] += red[256 + tid + st];
            }
            __syncthreads();
        }
        if (tid == 0 && out_size > NTOT) {
            float inv = 1.0f / (float)NTOT;
            float m = red[0] * inv;
            out[NTOT] = 0.25f * m * m + red[256] * inv;
        }
    }
}

// ---------------- host launch ----------------
extern "C" void kernel_launch(void* const* d_in, const int* in_sizes, int n_in,
                              void* d_out, int out_size) {
    const float* x   = (const float*)d_in[0];
    const float* emb = (const float*)d_in[1];
    if (n_in >= 2 && in_sizes[0] == K_CODES * D_DIM && in_sizes[1] == NTOT) {
        emb = (const float*)d_in[0];
        x   = (const float*)d_in[1];
    }
    float* out = (float*)d_out;

    prep<<<144, 256>>>(emb);
    dummy_k<<<1, 32>>>(0);     // position padding: vq_gemm stays at capture slot #4
    dummy_k<<<1, 32>>>(1);
    vq_gemm<<<GEMM_CTAS, 256>>>(x);
    vq_fallback<<<FB_CTAS, 256>>>(x, emb);
    vq_gather<<<GATHER_BLOCKS, 256>>>(x, out, out_size);
}

// round 17
// speedup vs baseline: 1.6403x; 1.4381x over previous
#include <cuda_runtime.h>
#include <cuda_fp16.h>
#include <cstdint>

#define K_CODES 4096
#define D_DIM   64
#define N_ROWS  65536
#define NTOT    (N_ROWS * D_DIM)
#define NPC     32
#define NCHUNK  (K_CODES / NPC)      // 128
#define GEMM_CTAS (N_ROWS / 256)     // 256 (256 rows per CTA, 32 per warp)
#define MARGIN  1.25e-3f
#define GATHER_BLOCKS 1024
#define FLT_BIG 3.0e38f
#define FB_ROWS 4
#define FB_SLICES 8
#define FB_CTAS 2048

// ---------------- global scratch ----------------
__device__ float g_eT[K_CODES * D_DIM];
__device__ float g_enorm[K_CODES];
__device__ float g_enfrag[K_CODES];
__device__ int   g_idx[N_ROWS];
__device__ int   g_nflag;
__device__ int   g_fbdone;
__device__ int   g_gadone;
__device__ int   g_flagrows[N_ROWS];
__device__ unsigned long long g_key[N_ROWS];
__device__ float g_p1[GATHER_BLOCKS];
__device__ float g_p2[GATHER_BLOCKS];
__device__ __align__(16) uint4 g_Bfrag[NCHUNK * 4 * 2 * 32];    // 512 KB

// ---------------- asm helpers ----------------
#define MMA16816(d, a, b0, b1) \
    asm volatile("mma.sync.aligned.m16n8k16.row.col.f32.f16.f16.f32 " \
        "{%0,%1,%2,%3}, {%4,%5,%6,%7}, {%8,%9}, {%0,%1,%2,%3};" \
        : "+f"((d)[0]), "+f"((d)[1]), "+f"((d)[2]), "+f"((d)[3]) \
        : "r"((a)[0]), "r"((a)[1]), "r"((a)[2]), "r"((a)[3]), "r"(b0), "r"(b1))

static __device__ __forceinline__ uint32_t h2u(__half2 h) {
    union { __half2 h; uint32_t u; } c; c.h = h; return c.u;
}
static __device__ __forceinline__ uint32_t f2tohalf2(float a, float b) {
    return h2u(__floats2half2_rn(a, b));
}
static __device__ __forceinline__ uint32_t ord_f32(float s) {
    uint32_t u = __float_as_uint(s);
    return (u & 0x80000000u) ? ~u : (u | 0x80000000u);
}

// ---------------- fused prep: blocks 0-15 norms/eT/enfrag, blocks 16-143 Bfrag ----------------
__global__ void prep(const float* __restrict__ emb) {
    const int tid = threadIdx.x;
    if (blockIdx.x < 16) {
        int n = blockIdx.x * 256 + tid;
        if (n == 0) { g_nflag = 0; g_fbdone = 0; g_gadone = 0; }
        float acc = 0.0f;
#pragma unroll
        for (int d = 0; d < D_DIM; ++d) {
            float v = __ldg(&emb[d * K_CODES + n]);
            g_eT[n * D_DIM + d] = v;
            acc += v * v;
        }
        g_enorm[n] = acc;
        int c = n >> 5, r = n & 31;
        int j = r >> 3, p = (r & 7) >> 1, e = r & 1;
        g_enfrag[(((c * 4 + j) * 4) + p) * 2 + e] = acc;
    } else {
        int id = (blockIdx.x - 16) * 256 + tid;   // 0 .. 32767
        int l = id & 31;
        int q = (id >> 5) & 1;
        int s = (id >> 6) & 3;
        int c = id >> 8;
        uint32_t w[4];
#pragma unroll
        for (int jj = 0; jj < 2; ++jj) {
            int n  = c * 32 + (2 * q + jj) * 8 + (l >> 2);
            int d0 = s * 16 + (l & 3) * 2;
            float b00 = __ldg(&emb[(d0    ) * K_CODES + n]);
            float b01 = __ldg(&emb[(d0 + 1) * K_CODES + n]);
            float b10 = __ldg(&emb[(d0 + 8) * K_CODES + n]);
            float b11 = __ldg(&emb[(d0 + 9) * K_CODES + n]);
            w[jj * 2]     = f2tohalf2(b00, b01);
            w[jj * 2 + 1] = f2tohalf2(b10, b11);
        }
        g_Bfrag[id] = make_uint4(w[0], w[1], w[2], w[3]);
    }
}

// ---------------- main GEMM: R13 body (32 rows/warp, best measured) ----------------
__global__ __launch_bounds__(256) void vq_gemm(const float* __restrict__ x) {
    const int tid  = threadIdx.x;
    const int lane = tid & 31;
    const int w    = tid >> 5;
    const int rowBase = blockIdx.x * 256 + w * 32;

    uint32_t afr[2][4][4];
#pragma unroll
    for (int t = 0; t < 2; ++t) {
        const int rA = rowBase + t * 16 + (lane >> 2);
        const int kc = (lane & 3) * 2;
#pragma unroll
        for (int s = 0; s < 4; ++s) {
            const float* p0 = x + (size_t)rA * 64 + s * 16 + kc;
            const float* p1 = p0 + 8 * 64;
            float2 a0 = __ldg((const float2*)p0);
            float2 a1 = __ldg((const float2*)p1);
            float2 a2 = __ldg((const float2*)(p0 + 8));
            float2 a3 = __ldg((const float2*)(p1 + 8));
            afr[t][s][0] = f2tohalf2(a0.x, a0.y);
            afr[t][s][1] = f2tohalf2(a1.x, a1.y);
            afr[t][s][2] = f2tohalf2(a2.x, a2.y);
            afr[t][s][3] = f2tohalf2(a3.x, a3.y);
        }
    }

    float m1[2][2], m2[2][2];
    int   idx[2][2];
#pragma unroll
    for (int t = 0; t < 2; ++t)
#pragma unroll
        for (int h = 0; h < 2; ++h) { m1[t][h] = FLT_BIG; m2[t][h] = FLT_BIG; idx[t][h] = 0; }

    const uint4* bp = g_Bfrag + lane;
    const float2* enf = (const float2*)g_enfrag + (lane & 3);

    for (int c = 0; c < NCHUNK; ++c) {
        float acc0[4][4], acc1[4][4];
#pragma unroll
        for (int j = 0; j < 4; ++j)
#pragma unroll
            for (int i = 0; i < 4; ++i) { acc0[j][i] = 0.0f; acc1[j][i] = 0.0f; }

#pragma unroll
        for (int s = 0; s < 4; ++s) {
            uint4 B0 = __ldg(bp);
            uint4 B1 = __ldg(bp + 32);
            bp += 64;
            MMA16816(acc0[0], afr[0][s], B0.x, B0.y);
            MMA16816(acc0[1], afr[0][s], B0.z, B0.w);
            MMA16816(acc0[2], afr[0][s], B1.x, B1.y);
            MMA16816(acc0[3], afr[0][s], B1.z, B1.w);
            MMA16816(acc1[0], afr[1][s], B0.x, B0.y);
            MMA16816(acc1[1], afr[1][s], B0.z, B0.w);
            MMA16816(acc1[2], afr[1][s], B1.x, B1.y);
            MMA16816(acc1[3], afr[1][s], B1.z, B1.w);
        }

        float2 en[4];
#pragma unroll
        for (int j = 0; j < 4; ++j)
            en[j] = __ldg(enf + (size_t)(c * 4 + j) * 4);

#pragma unroll
        for (int t = 0; t < 2; ++t) {
            float s0[8], s1[8];
#pragma unroll
            for (int j = 0; j < 4; ++j) {
                const float (*ac)[4] = (t == 0) ? acc0 : acc1;
                s0[2 * j]     = fmaf(-2.0f, ac[j][0], en[j].x);
                s0[2 * j + 1] = fmaf(-2.0f, ac[j][1], en[j].y);
                s1[2 * j]     = fmaf(-2.0f, ac[j][2], en[j].x);
                s1[2 * j + 1] = fmaf(-2.0f, ac[j][3], en[j].y);
            }
            float cA = fminf(fminf(fminf(s0[0], s0[1]), fminf(s0[2], s0[3])),
                             fminf(fminf(s0[4], s0[5]), fminf(s0[6], s0[7])));
            float cB = fminf(fminf(fminf(s1[0], s1[1]), fminf(s1[2], s1[3])),
                             fminf(fminf(s1[4], s1[5]), fminf(s1[6], s1[7])));

            if (cA < m1[t][0] || cB < m1[t][1]) {
                const int nb = c * 32 + (lane & 3) * 2;
                if (cA < m1[t][0]) {
                    float v1 = FLT_BIG, v2 = FLT_BIG; int id = 0;
#pragma unroll
                    for (int i = 0; i < 8; ++i) {
                        int n = nb + (i >> 1) * 8 + (i & 1);
                        float tt = fmaxf(v1, s0[i]);
                        bool  p  = s0[i] < v1;
                        v1 = fminf(v1, s0[i]);
                        v2 = fminf(v2, tt);
                        id = p ? n : id;
                    }
                    m2[t][0] = fminf(m1[t][0], v2); m1[t][0] = v1; idx[t][0] = id;
                } else {
                    m2[t][0] = fminf(m2[t][0], cA);
                }
                if (cB < m1[t][1]) {
                    float v1 = FLT_BIG, v2 = FLT_BIG; int id = 0;
#pragma unroll
                    for (int i = 0; i < 8; ++i) {
                        int n = nb + (i >> 1) * 8 + (i & 1);
                        float tt = fmaxf(v1, s1[i]);
                        bool  p  = s1[i] < v1;
                        v1 = fminf(v1, s1[i]);
                        v2 = fminf(v2, tt);
                        id = p ? n : id;
                    }
                    m2[t][1] = fminf(m1[t][1], v2); m1[t][1] = v1; idx[t][1] = id;
                } else {
                    m2[t][1] = fminf(m2[t][1], cB);
                }
            } else {
                m2[t][0] = fminf(m2[t][0], cA);
                m2[t][1] = fminf(m2[t][1], cB);
            }
        }
    }

#pragma unroll
    for (int t = 0; t < 2; ++t) {
#pragma unroll
        for (int h = 0; h < 2; ++h) {
#pragma unroll
            for (int off = 1; off <= 2; off <<= 1) {
                float om1 = __shfl_xor_sync(0xffffffffu, m1[t][h], off);
                float om2 = __shfl_xor_sync(0xffffffffu, m2[t][h], off);
                int   oid = __shfl_xor_sync(0xffffffffu, idx[t][h], off);
                m2[t][h] = fminf(fminf(m2[t][h], om2), fmaxf(m1[t][h], om1));
                bool p = (om1 < m1[t][h]) || (om1 == m1[t][h] && oid < idx[t][h]);
                m1[t][h] = p ? om1 : m1[t][h];
                idx[t][h] = p ? oid : idx[t][h];
            }
        }
    }

    if ((lane & 3) == 0) {
#pragma unroll
        for (int t = 0; t < 2; ++t) {
#pragma unroll
            for (int h = 0; h < 2; ++h) {
                int row0 = rowBase + t * 16 + h * 8 + (lane >> 2);
                g_idx[row0] = idx[t][h];
                if (m2[t][h] - m1[t][h] < MARGIN) {
                    g_key[row0] = ~0ull;
                    int p = atomicAdd(&g_nflag, 1); g_flagrows[p] = row0;
                }
            }
        }
    }
}

// ---------------- exact fp32 fallback: 8 k-slices, code-pair/thread, fused resolve ----------------
__global__ __launch_bounds__(256) void vq_fallback(const float* __restrict__ x,
                                                   const float* __restrict__ emb) {
    __shared__ float xr[FB_ROWS][64];
    __shared__ int s_last;
    const int tid  = threadIdx.x;
    const int lane = tid & 31;
    const int nf = g_nflag;
    const int nwork = ((nf + FB_ROWS - 1) / FB_ROWS) * FB_SLICES;

    for (int wk = (int)blockIdx.x; wk < nwork; wk += gridDim.x) {
        const int g  = wk / FB_SLICES;
        const int sl = wk % FB_SLICES;
        const int base = g * FB_ROWS;
        const int nr = min(FB_ROWS, nf - base);
        __syncthreads();
        {
            int r = tid >> 6, d = tid & 63;
            if (r < nr) xr[r][d] = x[(size_t)g_flagrows[base + r] * 64 + d];
        }
        __syncthreads();

        const int k0 = sl * 512 + tid;        // pair: (k0, k0+256)
        float dot0[FB_ROWS], dot1[FB_ROWS];
#pragma unroll
        for (int r = 0; r < FB_ROWS; ++r) { dot0[r] = 0.0f; dot1[r] = 0.0f; }
#pragma unroll
        for (int d4 = 0; d4 < 16; ++d4) {
            float4 xv[FB_ROWS];
#pragma unroll
            for (int r = 0; r < FB_ROWS; ++r)
                xv[r] = *(const float4*)&xr[r][d4 * 4];
#pragma unroll
            for (int dd = 0; dd < 4; ++dd) {
                float e0 = __ldg(&emb[(d4 * 4 + dd) * K_CODES + k0]);
                float e1 = __ldg(&emb[(d4 * 4 + dd) * K_CODES + k0 + 256]);
#pragma unroll
                for (int r = 0; r < FB_ROWS; ++r) {
                    float xc = ((const float*)&xv[r])[dd];
                    dot0[r] = fmaf(xc, e0, dot0[r]);
                    dot1[r] = fmaf(xc, e1, dot1[r]);
                }
            }
        }
        float en0 = __ldg(&g_enorm[k0]);
        float en1 = __ldg(&g_enorm[k0 + 256]);

        unsigned long long key[FB_ROWS];
#pragma unroll
        for (int r = 0; r < FB_ROWS; ++r) {
            float s0 = fmaf(-2.0f, dot0[r], en0);
            float s1 = fmaf(-2.0f, dot1[r], en1);
            bool take1 = s1 < s0;
            float sm = take1 ? s1 : s0;
            int   km = take1 ? (k0 + 256) : k0;
            key[r] = ((unsigned long long)ord_f32(sm) << 32) | (unsigned)km;
        }
#pragma unroll
        for (int off = 16; off > 0; off >>= 1) {
#pragma unroll
            for (int r = 0; r < FB_ROWS; ++r) {
                unsigned long long ok = __shfl_xor_sync(0xffffffffu, key[r], off);
                key[r] = ok < key[r] ? ok : key[r];
            }
        }
        if (lane == 0) {
#pragma unroll
            for (int r = 0; r < FB_ROWS; ++r)
                if (r < nr) atomicMin(&g_key[g_flagrows[base + r]], key[r]);
        }
    }

    __threadfence();
    if (tid == 0) s_last = (atomicAdd(&g_fbdone, 1) == (int)gridDim.x - 1);
    __syncthreads();
    if (s_last) {
        __threadfence();
        for (int i = tid; i < nf; i += 256) {
            int row = g_flagrows[i];
            g_idx[row] = (int)(g_key[row] & 0xFFFFFFFFu);
        }
    }
}

// ---------------- gather + loss (16 elems/thread, fused finalize) ----------------
__global__ __launch_bounds__(256) void vq_gather(const float* __restrict__ x,
                                                 float* __restrict__ out, int out_size) {
    __shared__ float red[512];
    __shared__ int s_last;
    const int tid = threadIdx.x;
    float s1 = 0.0f, s2 = 0.0f;
    int base = blockIdx.x * 4096 + tid;
#pragma unroll
    for (int j = 0; j < 16; ++j) {
        int i = base + j * 256;
        int row = i >> 6, d = i & 63;
        float q  = g_eT[g_idx[row] * 64 + d];
        float xv = x[i];
        out[i] = q;
        float dd = q - xv;
        s1 += dd;
        s2 += dd * dd;
    }
    red[tid] = s1; red[256 + tid] = s2;
    __syncthreads();
    for (int st = 128; st > 0; st >>= 1) {
        if (tid < st) {
            red[tid]       += red[tid + st];
            red[256 + tid] += red[256 + tid + st];
        }
        __syncthreads();
    }
    if (tid == 0) {
        g_p1[blockIdx.x] = red[0];
        g_p2[blockIdx.x] = red[256];
        __threadfence();
        s_last = (atomicAdd(&g_gadone, 1) == (int)gridDim.x - 1);
    }
    __syncthreads();
    if (s_last) {
        __threadfence();
        float a1 = g_p1[tid] + g_p1[tid + 256] + g_p1[tid + 512] + g_p1[tid + 768];
        float a2 = g_p2[tid] + g_p2[tid + 256] + g_p2[tid + 512] + g_p2[tid + 768];
        __syncthreads();
        red[tid] = a1; red[256 + tid] = a2;
        __syncthreads();
        for (int st = 128; st > 0; st >>= 1) {
            if (tid < st) {
                red[tid]       += red[tid + st];
                red[256 + tid] += red[256 + tid + st];
            }
            __syncthreads();
        }
        if (tid == 0 && out_size > NTOT) {
            float inv = 1.0f / (float)NTOT;
            float m = red[0] * inv;
            out[NTOT] = 0.25f * m * m + red[256] * inv;
        }
    }
}

// ---------------- host launch ----------------
extern "C" void kernel_launch(void* const* d_in, const int* in_sizes, int n_in,
                              void* d_out, int out_size) {
    const float* x   = (const float*)d_in[0];
    const float* emb = (const float*)d_in[1];
    if (n_in >= 2 && in_sizes[0] == K_CODES * D_DIM && in_sizes[1] == NTOT) {
        emb = (const float*)d_in[0];
        x   = (const float*)d_in[1];
    }
    float* out = (float*)d_out;

    prep<<<144, 256>>>(emb);
    vq_gemm<<<GEMM_CTAS, 256>>>(x);
    vq_fallback<<<FB_CTAS, 256>>>(x, emb);
    vq_gather<<<GATHER_BLOCKS, 256>>>(x, out, out_size);
}